// round 15
// baseline (speedup 1.0000x reference)
#include <cuda_runtime.h>
#include <cuda_fp16.h>
#include <math.h>
#include <stdint.h>

#define NPTS  2048
#define BATCH 8
#define BNT   (BATCH*NPTS)   // 16384
#define KNN   20

// ------------------------- scratch (device globals) -------------------------
__device__ float    d_uv[(size_t)BNT*512];    // v columns (blk-1 layout), width 2*O
__device__ __half   d_uh[(size_t)BNT*256];    // u in fp16, width O (gather source)
__device__ __half   d_umax[(size_t)BNT*256];  // fp16 (lossless: max of fp16 values)
__device__ __half   d_umin[(size_t)BNT*256];
__device__ __half   d_cat_hi[(size_t)BNT*512];
__device__ __half   d_cat_lo[(size_t)BNT*512];
__device__ float    d_h5[(size_t)BNT*1024];
__device__ int      d_idx[BNT*KNN];
__device__ float    d_wcomb[128*3];           // fp32 (block 1, K=3)
__device__ __half   d_wch[98304];
__device__ __half   d_wcl[98304];
__device__ __half   d_w5h[1024*512];
__device__ double   d_sum[1024];              // 4 regions of 256 (per edge block)
__device__ double   d_sumsq[1024];
__device__ float    d_psum[1024];             // head stats (fp32 atomics)
__device__ float    d_psumsq[1024];
__device__ float    d_bnsc[1024];
__device__ float    d_bnsh[1024];
__device__ unsigned d_gcnt[4];                // gather completion counters

// accurate tanh (edge blocks): (e^2x - 1)/(e^2x + 1)
__device__ __forceinline__ float ftanh(float x) {
    x = fminf(fmaxf(x, -15.f), 15.f);
    float e = __expf(2.f * x);
    return __fdividef(e - 1.f, e + 1.f);
}
// HW tanh (final layer)
__device__ __forceinline__ float ftanh_hw(float x) {
    float r;
    asm("tanh.approx.f32 %0, %1;" : "=f"(r) : "f"(x));
    return r;
}

__device__ __forceinline__ uint32_t smem_u32(const void* p) {
    uint32_t a;
    asm("{ .reg .u64 t; cvta.to.shared.u64 t, %1; cvt.u32.u64 %0, t; }"
        : "=r"(a) : "l"(p));
    return a;
}
#define SWZ128(off) ((off) ^ (((off) >> 3) & 0x70))

__device__ __forceinline__ void cp16(uint32_t dst, const void* src) {
    asm volatile("cp.async.cg.shared.global [%0], [%1], 16;"
                 :: "r"(dst), "l"(src) : "memory");
}
__device__ __forceinline__ void ldsm4(uint32_t& r0, uint32_t& r1, uint32_t& r2,
                                      uint32_t& r3, uint32_t addr) {
    asm volatile("ldmatrix.sync.aligned.m8n8.x4.shared.b16 {%0,%1,%2,%3}, [%4];"
                 : "=r"(r0), "=r"(r1), "=r"(r2), "=r"(r3) : "r"(addr));
}
__device__ __forceinline__ void ldsm2(uint32_t& r0, uint32_t& r1, uint32_t addr) {
    asm volatile("ldmatrix.sync.aligned.m8n8.x2.shared.b16 {%0,%1}, [%2];"
                 : "=r"(r0), "=r"(r1) : "r"(addr));
}
__device__ __forceinline__ void mma16816(float* d, const uint32_t* a, const uint32_t* b) {
    asm volatile("mma.sync.aligned.m16n8k16.row.col.f32.f16.f16.f32 "
                 "{%0,%1,%2,%3}, {%4,%5,%6,%7}, {%8,%9}, {%0,%1,%2,%3};"
                 : "+f"(d[0]), "+f"(d[1]), "+f"(d[2]), "+f"(d[3])
                 : "r"(a[0]), "r"(a[1]), "r"(a[2]), "r"(a[3]),
                   "r"(b[0]), "r"(b[1]));
}

// -------------- merged prep (blocks 0..2405) + KNN (blocks 2406..2533) ------
#define PREP_BLOCKS 2406
#define KNN_BLOCKS  (BATCH*16)

__device__ __forceinline__ void split_w(const float* __restrict__ w, int C, int O,
                                        int j, __half* dh, __half* dl) {
    int r = j / C, c = j - r*C;
    float v = (r < O) ? w[r*2*C + c]
                      : (w[(r-O)*2*C + C + c] - w[(r-O)*2*C + c]);
    __half hi = __float2half_rn(v);
    dh[j] = hi;
    dl[j] = __float2half_rn(v - __half2float(hi));
}

__global__ __launch_bounds__(256) void prep_knn(
    const float* __restrict__ w1, const float* __restrict__ w2,
    const float* __restrict__ w3, const float* __restrict__ w4,
    const float* __restrict__ w5, const float* __restrict__ x)
{
    if (blockIdx.x < PREP_BLOCKS) {
        int i = blockIdx.x*256 + threadIdx.x;
        if (i < 1024) {
            d_sum[i] = 0.0; d_sumsq[i] = 0.0;
            d_psum[i] = 0.f; d_psumsq[i] = 0.f;
            if (i < 4) d_gcnt[i] = 0u;
        } else if (i < 1408) {
            int j = i - 1024;
            int r = j / 3, c = j - r*3;
            float v = (r < 64) ? w1[r*6 + c] : (w1[(r-64)*6 + 3 + c] - w1[(r-64)*6 + c]);
            d_wcomb[j] = v;
        } else if (i < 9600) {
            split_w(w2, 64, 64, i - 1408, d_wch, d_wcl);
        } else if (i < 25984) {
            split_w(w3, 64, 128, i - 9600, d_wch + 8192, d_wcl + 8192);
        } else if (i < 91520) {
            split_w(w4, 128, 256, i - 25984, d_wch + 24576, d_wcl + 24576);
        } else if (i < 615808) {
            int j = i - 91520;
            d_w5h[j] = __float2half_rn(w5[j]);
        }
        return;
    }
    // ---- KNN part: 128 queries per block, 256 threads (all load smem) ----
    __shared__ float sx[NPTS*3];
    __shared__ float sxx[NPTS];
    int kb = blockIdx.x - PREP_BLOCKS;
    int b = kb >> 4;
    int qbase = (kb & 15) * 128;
    const float* xb = x + (size_t)b*NPTS*3;
    for (int i = threadIdx.x; i < NPTS*3; i += 256) sx[i] = xb[i];
    __syncthreads();
    for (int i = threadIdx.x; i < NPTS; i += 256) {
        float a0=sx[3*i], a1=sx[3*i+1], a2=sx[3*i+2];
        sxx[i] = a0*a0 + a1*a1 + a2*a2;
    }
    __syncthreads();
    if (threadIdx.x >= 128) return;
    int q = qbase + threadIdx.x;
    float qx=sx[3*q], qy=sx[3*q+1], qz=sx[3*q+2], qq=sxx[q];
    float best[KNN]; int bidx[KNN];
#pragma unroll
    for (int j=0;j<KNN;j++){ best[j]=-3.4e38f; bidx[j]=0; }
    float thr = -3.4e38f;
    for (int m=0;m<NPTS;m++){
        float pd = 2.f*(qx*sx[3*m]+qy*sx[3*m+1]+qz*sx[3*m+2]) - qq - sxx[m];
        if (pd > thr) {
            float ins = pd; int insi = m;
#pragma unroll
            for (int j=0;j<KNN;j++){
                float bj = best[j]; int ij = bidx[j];
                bool sw = bj < ins;
                best[j] = sw ? ins  : bj;
                bidx[j] = sw ? insi : ij;
                ins     = sw ? bj   : ins;
                insi    = sw ? ij   : insi;
            }
            thr = best[KNN-1];
        }
    }
    int base = (b*NPTS+q)*KNN;
#pragma unroll
    for (int j=0;j<KNN;j++) d_idx[base+j] = bidx[j];
}

// --- HMMA GEMM (NT, fp16, terms in {1,3}, cp.async double-buffered) ---------
__global__ __launch_bounds__(256) void gemm_mma(
    const __half* __restrict__ Ah, const __half* __restrict__ Al, int lda,
    const __half* __restrict__ Bh, const __half* __restrict__ Bl, int ldb,
    float* __restrict__ C, int ldc, int Kdim, int terms,
    __half* Uh, int u_cols,
    float* psum, float* psumsq)
{
    extern __shared__ __align__(128) uint8_t smemraw[];
    uint32_t sbase = smem_u32(smemraw);
    int tid = threadIdx.x;
    int lane = tid & 31, wid = tid >> 5;
    int warp_m = wid >> 2, warp_n = wid & 3;
    int bm = blockIdx.y*128, bn = blockIdx.x*128;

    float acc[4][4][4] = {};

    int base = Kdim >> 6;          // k-tiles per region
    int ktiles = terms*base;

    {
#pragma unroll
        for (int i = 0; i < 4; i++) {
            int u = tid + i*256;
            int r = u >> 3, cb = (u & 7) << 4;
            cp16(sbase + SWZ128(r*128 + cb),         Ah + (size_t)(bm + r)*lda + (cb >> 1));
            cp16(sbase + 16384 + SWZ128(r*128 + cb), Bh + (size_t)(bn + r)*ldb + (cb >> 1));
        }
        asm volatile("cp.async.commit_group;" ::: "memory");
    }

    for (int it = 0; it < ktiles; it++) {
        if (it + 1 < ktiles) {
            int nt2 = it + 1;
            int grp = nt2 / base;
            int kk = (nt2 - grp*base) << 6;
            const __half* Ap = (grp == 1) ? Al : Ah;
            const __half* Bp = (grp == 2) ? Bl : Bh;
            uint32_t sa = sbase + ((nt2 & 1) ? 32768u : 0u);
#pragma unroll
            for (int i = 0; i < 4; i++) {
                int u = tid + i*256;
                int r = u >> 3, cb = (u & 7) << 4;
                cp16(sa + SWZ128(r*128 + cb),         Ap + (size_t)(bm + r)*lda + kk + (cb >> 1));
                cp16(sa + 16384 + SWZ128(r*128 + cb), Bp + (size_t)(bn + r)*ldb + kk + (cb >> 1));
            }
            asm volatile("cp.async.commit_group;" ::: "memory");
            asm volatile("cp.async.wait_group 1;" ::: "memory");
        } else {
            asm volatile("cp.async.wait_group 0;" ::: "memory");
        }
        __syncthreads();

        uint32_t sA = sbase + ((it & 1) ? 32768u : 0u);
        uint32_t sB = sA + 16384;
#pragma unroll
        for (int ks = 0; ks < 4; ks++) {
            int kb = ks*32;
            uint32_t a[4][4], b[4][2];
#pragma unroll
            for (int mt = 0; mt < 4; mt++) {
                int row = warp_m*64 + mt*16 + (lane & 15);
                uint32_t ad = sA + SWZ128((uint32_t)(row*128 + kb + ((lane >> 4) << 4)));
                ldsm4(a[mt][0], a[mt][1], a[mt][2], a[mt][3], ad);
            }
#pragma unroll
            for (int nt = 0; nt < 4; nt++) {
                int row = warp_n*32 + nt*8 + (lane & 7);
                uint32_t ad = sB + SWZ128((uint32_t)(row*128 + kb + (((lane >> 3) & 1) << 4)));
                ldsm2(b[nt][0], b[nt][1], ad);
            }
#pragma unroll
            for (int mt = 0; mt < 4; mt++)
#pragma unroll
                for (int nt = 0; nt < 4; nt++)
                    mma16816(acc[mt][nt], a[mt], b[nt]);
        }
        __syncthreads();
    }

#pragma unroll
    for (int mt = 0; mt < 4; mt++) {
        int r0 = bm + warp_m*64 + mt*16 + (lane >> 2);
#pragma unroll
        for (int nt = 0; nt < 4; nt++) {
            int c0 = bn + warp_n*32 + nt*8 + ((lane & 3) << 1);
            if (Uh && c0 < u_cols) {
                *(__half2*)&Uh[(size_t)r0*u_cols + c0] =
                    __floats2half2_rn(acc[mt][nt][0], acc[mt][nt][1]);
                *(__half2*)&Uh[(size_t)(r0+8)*u_cols + c0] =
                    __floats2half2_rn(acc[mt][nt][2], acc[mt][nt][3]);
            } else {
                *(float2*)&C[(size_t)r0*ldc + c0]     = make_float2(acc[mt][nt][0], acc[mt][nt][1]);
                *(float2*)&C[(size_t)(r0+8)*ldc + c0] = make_float2(acc[mt][nt][2], acc[mt][nt][3]);
            }
        }
    }

    if (psum) {
#pragma unroll
        for (int nt = 0; nt < 4; nt++) {
            float s0=0.f, s1=0.f, q0=0.f, q1=0.f;
#pragma unroll
            for (int mt = 0; mt < 4; mt++) {
                float v0=acc[mt][nt][0], v1=acc[mt][nt][1];
                float v2=acc[mt][nt][2], v3=acc[mt][nt][3];
                s0 += v0+v2; s1 += v1+v3;
                q0 += v0*v0 + v2*v2; q1 += v1*v1 + v3*v3;
            }
#pragma unroll
            for (int off = 16; off >= 4; off >>= 1) {
                s0 += __shfl_down_sync(0xffffffffu, s0, off);
                s1 += __shfl_down_sync(0xffffffffu, s1, off);
                q0 += __shfl_down_sync(0xffffffffu, q0, off);
                q1 += __shfl_down_sync(0xffffffffu, q1, off);
            }
            if (lane < 4) {
                int c0 = bn + warp_n*32 + nt*8 + lane*2;
                atomicAdd(&psum[c0],     s0);
                atomicAdd(&psum[c0+1],   s1);
                atomicAdd(&psumsq[c0],   q0);
                atomicAdd(&psumsq[c0+1], q1);
            }
        }
    }
}

// ------------------------- block-1 projection (K=3) -------------------------
__global__ __launch_bounds__(256) void uv1_kernel(const float* __restrict__ ft) {
    int p = blockIdx.x*2 + (threadIdx.x >> 7);
    int o = threadIdx.x & 127;
    float x0 = ft[p*3], x1 = ft[p*3+1], x2 = ft[p*3+2];
    float r = x0*d_wcomb[o*3] + x1*d_wcomb[o*3+1] + x2*d_wcomb[o*3+2];
    if (o < 64) d_uh[(size_t)p*64 + o] = __float2half_rn(r);
    else        d_uv[(size_t)p*128 + o] = r;
}

// ---- gather + BN stats (fp16 u, hmax2/hmin2) + last-block BN coefs ----------
__global__ __launch_bounds__(256) void gather_kernel(int O, int iters, int soff,
                                                     int blk,
                                                     const float* __restrict__ gw,
                                                     const float* __restrict__ bw,
                                                     float invcnt) {
    int tpp = O >> 1;
    int groups = 256 / tpp;
    int g = threadIdx.x / tpp;
    int c2 = threadIdx.x - g*tpp;
    int ppb = groups * iters;
    int p0 = blockIdx.x * ppb;
    int W2 = 2*O;
    float sx=0.f, sy=0.f, qx=0.f, qy=0.f;
    for (int it = 0; it < iters; it++) {
        int p = p0 + it*groups + g;
        int rbase = (p >> 11) << 11;
        const int* ip = d_idx + p*KNN;
        float s1x, s1y, s2x, s2y;
        __half2 hmx, hmn;
        {
            int m = ip[0];
            __half2 u2 = *(const __half2*)&d_uh[(size_t)(rbase + m)*O + 2*c2];
            hmx = u2; hmn = u2;
            float2 u = __half22float2(u2);
            s1x = u.x; s1y = u.y;
            s2x = u.x*u.x; s2y = u.y*u.y;
        }
#pragma unroll
        for (int k = 1; k < KNN; k++) {
            int m = ip[k];
            __half2 u2 = *(const __half2*)&d_uh[(size_t)(rbase + m)*O + 2*c2];
            hmx = __hmax2(hmx, u2);
            hmn = __hmin2(hmn, u2);
            float2 u = __half22float2(u2);
            s1x += u.x; s1y += u.y;
            s2x += u.x*u.x; s2y += u.y*u.y;
        }
        float2 v = *(const float2*)&d_uv[(size_t)p*W2 + O + 2*c2];
        *(__half2*)&d_umax[(size_t)p*O + 2*c2] = hmx;
        *(__half2*)&d_umin[(size_t)p*O + 2*c2] = hmn;
        sx += s1x + 20.f*v.x;  sy += s1y + 20.f*v.y;
        qx += s2x + 2.f*v.x*s1x + 20.f*v.x*v.x;
        qy += s2y + 2.f*v.y*s1y + 20.f*v.y*v.y;
    }
    __shared__ float ssx[256], ssy[256], sqx[256], sqy[256];
    ssx[threadIdx.x] = sx; ssy[threadIdx.x] = sy;
    sqx[threadIdx.x] = qx; sqy[threadIdx.x] = qy;
    __syncthreads();
    for (int s = groups >> 1; s >= 1; s >>= 1) {
        if (g < s) {
            int j = threadIdx.x + s*tpp;
            ssx[threadIdx.x] += ssx[j]; ssy[threadIdx.x] += ssy[j];
            sqx[threadIdx.x] += sqx[j]; sqy[threadIdx.x] += sqy[j];
        }
        __syncthreads();
    }
    if (g == 0) {
        atomicAdd(&d_sum[soff + 2*c2],     (double)ssx[c2]);
        atomicAdd(&d_sum[soff + 2*c2+1],   (double)ssy[c2]);
        atomicAdd(&d_sumsq[soff + 2*c2],   (double)sqx[c2]);
        atomicAdd(&d_sumsq[soff + 2*c2+1], (double)sqy[c2]);
        __threadfence();
    }
    __syncthreads();
    __shared__ int is_last;
    if (threadIdx.x == 0) {
        unsigned old = atomicAdd(&d_gcnt[blk], 1u);
        is_last = (old == gridDim.x - 1u) ? 1 : 0;
    }
    __syncthreads();
    if (is_last && threadIdx.x < O) {
        int o = threadIdx.x;
        __threadfence();
        float mean = (float)(d_sum[soff+o]   * (double)invcnt);
        float msq  = (float)(d_sumsq[soff+o] * (double)invcnt);
        float var  = fmaxf(msq - mean*mean, 0.f);
        float sc = gw[o] * rsqrtf(var + 1e-5f);
        d_bnsc[soff+o] = sc;
        d_bnsh[soff+o] = bw[o] - mean*sc;
    }
}

// ------------------ edge_out (2 channels / thread, hoisted coefs) -----------
__global__ void edge_out(int O, int coff, int soff) {
    int i = blockIdx.x*256 + threadIdx.x;      // one per 2 channels
    int half_O = O >> 1;
    if (i < BNT*half_O) {
        int p = i / half_O, c2 = i - p*half_O;
        int o = 2*c2;
        float2 sc = *(const float2*)&d_bnsc[soff+o];
        float2 sh = *(const float2*)&d_bnsh[soff+o];
        float2 umx = __half22float2(*(const __half2*)&d_umax[(size_t)p*O + o]);
        float2 umn = __half22float2(*(const __half2*)&d_umin[(size_t)p*O + o]);
        float2 v   = *(const float2*)&d_uv[(size_t)p*(2*O) + O + o];
        float e0 = (sc.x >= 0.f) ? umx.x : umn.x;
        float e1 = (sc.y >= 0.f) ? umx.y : umn.y;
        float t0 = ftanh((v.x + e0)*sc.x + sh.x);
        float t1 = ftanh((v.y + e1)*sc.y + sh.y);
        __half2 hi = __floats2half2_rn(t0, t1);
        float r0 = __half2float(__low2half(hi));
        float r1 = __half2float(__high2half(hi));
        __half2 lo = __floats2half2_rn(t0 - r0, t1 - r1);
        size_t cidx = (size_t)p*512 + coff + o;
        *(__half2*)&d_cat_hi[cidx] = hi;
        *(__half2*)&d_cat_lo[cidx] = lo;
    }
}

// ------------------------- head: final reduce --------------------------------
__global__ __launch_bounds__(256) void final5(const float* __restrict__ g5,
                                              const float* __restrict__ b5,
                                              float* __restrict__ out) {
    int ol = threadIdx.x & 31;
    int row = threadIdx.x >> 5;
    int b = blockIdx.y;
    int o = blockIdx.x*32 + ol;
    float inv = 1.f / (float)BNT;
    float mean = d_psum[o] * inv;
    float var = fmaxf(d_psumsq[o]*inv - mean*mean, 0.f);
    float sc = g5[o] * rsqrtf(var + 1e-5f);
    float sh = b5[o] - mean*sc;
    const float* hp = &d_h5[(size_t)(b*NPTS)*1024 + o];
    float mx0=-3.4e38f, mx1=-3.4e38f, mx2=-3.4e38f, mx3=-3.4e38f;
    float s0=0.f, s1=0.f, s2=0.f, s3=0.f;
    for (int n = row; n < NPTS; n += 32) {
        float z0 = hp[(size_t)n*1024];
        float z1 = hp[(size_t)(n+8)*1024];
        float z2 = hp[(size_t)(n+16)*1024];
        float z3 = hp[(size_t)(n+24)*1024];
        float t0 = ftanh_hw(z0*sc + sh);
        float t1 = ftanh_hw(z1*sc + sh);
        float t2 = ftanh_hw(z2*sc + sh);
        float t3 = ftanh_hw(z3*sc + sh);
        mx0 = fmaxf(mx0, t0); s0 += t0;
        mx1 = fmaxf(mx1, t1); s1 += t1;
        mx2 = fmaxf(mx2, t2); s2 += t2;
        mx3 = fmaxf(mx3, t3); s3 += t3;
    }
    float mx = fmaxf(fmaxf(mx0, mx1), fmaxf(mx2, mx3));
    float sm = (s0 + s1) + (s2 + s3);
    __shared__ float smx[8][32], ssm[8][32];
    smx[row][ol] = mx; ssm[row][ol] = sm;
    __syncthreads();
    if (row == 0) {
#pragma unroll
        for (int r=1;r<8;r++){ mx = fmaxf(mx, smx[r][ol]); sm += ssm[r][ol]; }
        out[b*2048 + o]        = mx;
        out[b*2048 + 1024 + o] = sm * (1.f/NPTS);
    }
}

// ------------------------------- launch -------------------------------------
#define GEMM_SMEM 65536

extern "C" void kernel_launch(void* const* d_in, const int* in_sizes, int n_in,
                              void* d_out, int out_size) {
    const float* x  = (const float*)d_in[0];
    const float* ft = (const float*)d_in[1];
    const float* W[4]  = {(const float*)d_in[2],  (const float*)d_in[5],
                          (const float*)d_in[8],  (const float*)d_in[11]};
    const float* G[4]  = {(const float*)d_in[3],  (const float*)d_in[6],
                          (const float*)d_in[9],  (const float*)d_in[12]};
    const float* Bv[4] = {(const float*)d_in[4],  (const float*)d_in[7],
                          (const float*)d_in[10], (const float*)d_in[13]};
    const float* w5 = (const float*)d_in[14];
    const float* g5 = (const float*)d_in[15];
    const float* b5 = (const float*)d_in[16];
    float* out = (float*)d_out;

    cudaFuncSetAttribute(gemm_mma, cudaFuncAttributeMaxDynamicSharedMemorySize,
                         GEMM_SMEM);

    void *puv, *puh, *pch, *pcl, *ph5, *pwch, *pwcl, *pw5h, *pps, *ppq;
    cudaGetSymbolAddress(&puv,  d_uv);
    cudaGetSymbolAddress(&puh,  d_uh);
    cudaGetSymbolAddress(&pch,  d_cat_hi);
    cudaGetSymbolAddress(&pcl,  d_cat_lo);
    cudaGetSymbolAddress(&ph5,  d_h5);
    cudaGetSymbolAddress(&pwch, d_wch);
    cudaGetSymbolAddress(&pwcl, d_wcl);
    cudaGetSymbolAddress(&pw5h, d_w5h);
    cudaGetSymbolAddress(&pps,  d_psum);
    cudaGetSymbolAddress(&ppq,  d_psumsq);
    float* uvP = (float*)puv;
    __half* uhP = (__half*)puh;
    __half* chP = (__half*)pch;
    __half* clP = (__half*)pcl;
    float* h5P = (float*)ph5;
    __half* wchP = (__half*)pwch;
    __half* wclP = (__half*)pwcl;
    __half* w5hP = (__half*)pw5h;

    prep_knn<<<PREP_BLOCKS + KNN_BLOCKS, 256>>>(W[0], W[1], W[2], W[3], w5, x);

    const int Cin[4]  = {3, 64, 64, 128};
    const int Oc[4]   = {64, 64, 128, 256};
    const int coff[4] = {0, 64, 128, 256};
    const int boff[4] = {0, 0, 8192, 24576};

    for (int blk = 0; blk < 4; blk++) {
        int C = Cin[blk], O = Oc[blk];
        if (blk == 0) {
            uv1_kernel<<<BNT/2, 256>>>(ft);
        } else {
            int cin = coff[blk-1];
            dim3 gg(2*O/128, BNT/128);
            gemm_mma<<<gg, 256, GEMM_SMEM>>>(chP + cin, clP + cin, 512,
                                             wchP + boff[blk], wclP + boff[blk], C,
                                             uvP, 2*O, C, 3, uhP, O,
                                             nullptr, nullptr);
        }
        int iters = 4;
        int tpp = O/2, groups = 256/tpp, ppb = groups*iters;
        gather_kernel<<<BNT/ppb, 256>>>(O, iters, blk*256, blk,
                                        G[blk], Bv[blk], 1.f/((float)BNT*KNN));
        edge_out<<<(BNT*(O/2) + 255)/256, 256>>>(O, coff[blk], blk*256);
    }

    dim3 g5g(1024/128, BNT/128);
    gemm_mma<<<g5g, 256, GEMM_SMEM>>>(chP, nullptr, 512, w5hP, nullptr, 512,
                                      h5P, 1024, 512, 1, nullptr, 0,
                                      (float*)pps, (float*)ppq);
    dim3 fg(32, BATCH);
    final5<<<fg, 256>>>(g5, b5, out);
}

// round 16
// speedup vs baseline: 1.4029x; 1.4029x over previous
#include <cuda_runtime.h>
#include <cuda_fp16.h>
#include <math.h>
#include <stdint.h>

#define NPTS  2048
#define BATCH 8
#define BNT   (BATCH*NPTS)   // 16384
#define KNN   20

// ------------------------- scratch (device globals) -------------------------
__device__ float    d_uv[(size_t)BNT*512];    // v columns (blk-1 layout), width 2*O
__device__ __half   d_uh[(size_t)BNT*256];    // u in fp16, width O (gather source)
__device__ float    d_umax[(size_t)BNT*256];
__device__ float    d_umin[(size_t)BNT*256];
__device__ __half   d_cat_hi[(size_t)BNT*512];
__device__ __half   d_cat_lo[(size_t)BNT*512];
__device__ __half   d_h5[(size_t)BNT*1024];   // head output in fp16
__device__ int      d_idx[BNT*KNN];
__device__ float    d_wcomb[128*3];           // fp32 (block 1, K=3)
__device__ __half   d_wch[98304];
__device__ __half   d_wcl[98304];
__device__ __half   d_w5h[1024*512];
__device__ double   d_sum[1024];              // 4 regions of 256 (per edge block)
__device__ double   d_sumsq[1024];
__device__ float    d_psum[1024];             // head stats (fp32 atomics, exact)
__device__ float    d_psumsq[1024];
__device__ float    d_bnsc[1024];
__device__ float    d_bnsh[1024];
__device__ unsigned d_gcnt[4];                // gather completion counters

// accurate tanh (edge blocks): (e^2x - 1)/(e^2x + 1)
__device__ __forceinline__ float ftanh(float x) {
    x = fminf(fmaxf(x, -15.f), 15.f);
    float e = __expf(2.f * x);
    return __fdividef(e - 1.f, e + 1.f);
}
// HW tanh (final layer)
__device__ __forceinline__ float ftanh_hw(float x) {
    float r;
    asm("tanh.approx.f32 %0, %1;" : "=f"(r) : "f"(x));
    return r;
}

__device__ __forceinline__ uint32_t smem_u32(const void* p) {
    uint32_t a;
    asm("{ .reg .u64 t; cvta.to.shared.u64 t, %1; cvt.u32.u64 %0, t; }"
        : "=r"(a) : "l"(p));
    return a;
}
#define SWZ128(off) ((off) ^ (((off) >> 3) & 0x70))

__device__ __forceinline__ void cp16(uint32_t dst, const void* src) {
    asm volatile("cp.async.cg.shared.global [%0], [%1], 16;"
                 :: "r"(dst), "l"(src) : "memory");
}
__device__ __forceinline__ void ldsm4(uint32_t& r0, uint32_t& r1, uint32_t& r2,
                                      uint32_t& r3, uint32_t addr) {
    asm volatile("ldmatrix.sync.aligned.m8n8.x4.shared.b16 {%0,%1,%2,%3}, [%4];"
                 : "=r"(r0), "=r"(r1), "=r"(r2), "=r"(r3) : "r"(addr));
}
__device__ __forceinline__ void ldsm2(uint32_t& r0, uint32_t& r1, uint32_t addr) {
    asm volatile("ldmatrix.sync.aligned.m8n8.x2.shared.b16 {%0,%1}, [%2];"
                 : "=r"(r0), "=r"(r1) : "r"(addr));
}
__device__ __forceinline__ void mma16816(float* d, const uint32_t* a, const uint32_t* b) {
    asm volatile("mma.sync.aligned.m16n8k16.row.col.f32.f16.f16.f32 "
                 "{%0,%1,%2,%3}, {%4,%5,%6,%7}, {%8,%9}, {%0,%1,%2,%3};"
                 : "+f"(d[0]), "+f"(d[1]), "+f"(d[2]), "+f"(d[3])
                 : "r"(a[0]), "r"(a[1]), "r"(a[2]), "r"(a[3]),
                   "r"(b[0]), "r"(b[1]));
}

// ----------------------- KNN (128 blocks x 128 threads) ---------------------
__global__ __launch_bounds__(128) void knn_kernel(const float* __restrict__ x) {
    __shared__ float sx[NPTS*3];
    __shared__ float sxx[NPTS];
    int b = blockIdx.x >> 4;
    int qbase = (blockIdx.x & 15) * 128;
    const float* xb = x + (size_t)b*NPTS*3;
    for (int i = threadIdx.x; i < NPTS*3; i += 128) sx[i] = xb[i];
    __syncthreads();
    for (int i = threadIdx.x; i < NPTS; i += 128) {
        float a0=sx[3*i], a1=sx[3*i+1], a2=sx[3*i+2];
        sxx[i] = a0*a0 + a1*a1 + a2*a2;
    }
    __syncthreads();
    int q = qbase + threadIdx.x;
    float qx=sx[3*q], qy=sx[3*q+1], qz=sx[3*q+2], qq=sxx[q];
    float best[KNN]; int bidx[KNN];
#pragma unroll
    for (int j=0;j<KNN;j++){ best[j]=-3.4e38f; bidx[j]=0; }
    float thr = -3.4e38f;
    for (int m=0;m<NPTS;m++){
        float pd = 2.f*(qx*sx[3*m]+qy*sx[3*m+1]+qz*sx[3*m+2]) - qq - sxx[m];
        if (pd > thr) {
            float ins = pd; int insi = m;
#pragma unroll
            for (int j=0;j<KNN;j++){
                float bj = best[j]; int ij = bidx[j];
                bool sw = bj < ins;
                best[j] = sw ? ins  : bj;
                bidx[j] = sw ? insi : ij;
                ins     = sw ? bj   : ins;
                insi    = sw ? ij   : insi;
            }
            thr = best[KNN-1];
        }
    }
    int base = (b*NPTS+q)*KNN;
#pragma unroll
    for (int j=0;j<KNN;j++) d_idx[base+j] = bidx[j];
}

// --- HMMA GEMM (NT, fp16, terms in {1,3}, cp.async double-buffered) ---------
// If Uh != nullptr: columns c0 < u_cols go to Uh (fp16); rest to C (fp32).
// If Ch != nullptr: all columns go to Ch (fp16, width ldc).
__global__ __launch_bounds__(256) void gemm_mma(
    const __half* __restrict__ Ah, const __half* __restrict__ Al, int lda,
    const __half* __restrict__ Bh, const __half* __restrict__ Bl, int ldb,
    float* __restrict__ C, __half* __restrict__ Ch, int ldc, int Kdim, int terms,
    __half* Uh, int u_cols,
    float* psum, float* psumsq)
{
    extern __shared__ __align__(128) uint8_t smemraw[];
    uint32_t sbase = smem_u32(smemraw);
    int tid = threadIdx.x;
    int lane = tid & 31, wid = tid >> 5;
    int warp_m = wid >> 2, warp_n = wid & 3;
    int bm = blockIdx.y*128, bn = blockIdx.x*128;

    float acc[4][4][4] = {};

    int base = Kdim >> 6;          // k-tiles per region
    int ktiles = terms*base;

    {
#pragma unroll
        for (int i = 0; i < 4; i++) {
            int u = tid + i*256;
            int r = u >> 3, cb = (u & 7) << 4;
            cp16(sbase + SWZ128(r*128 + cb),         Ah + (size_t)(bm + r)*lda + (cb >> 1));
            cp16(sbase + 16384 + SWZ128(r*128 + cb), Bh + (size_t)(bn + r)*ldb + (cb >> 1));
        }
        asm volatile("cp.async.commit_group;" ::: "memory");
    }

    for (int it = 0; it < ktiles; it++) {
        if (it + 1 < ktiles) {
            int nt2 = it + 1;
            int grp = nt2 / base;
            int kk = (nt2 - grp*base) << 6;
            const __half* Ap = (grp == 1) ? Al : Ah;
            const __half* Bp = (grp == 2) ? Bl : Bh;
            uint32_t sa = sbase + ((nt2 & 1) ? 32768u : 0u);
#pragma unroll
            for (int i = 0; i < 4; i++) {
                int u = tid + i*256;
                int r = u >> 3, cb = (u & 7) << 4;
                cp16(sa + SWZ128(r*128 + cb),         Ap + (size_t)(bm + r)*lda + kk + (cb >> 1));
                cp16(sa + 16384 + SWZ128(r*128 + cb), Bp + (size_t)(bn + r)*ldb + kk + (cb >> 1));
            }
            asm volatile("cp.async.commit_group;" ::: "memory");
            asm volatile("cp.async.wait_group 1;" ::: "memory");
        } else {
            asm volatile("cp.async.wait_group 0;" ::: "memory");
        }
        __syncthreads();

        uint32_t sA = sbase + ((it & 1) ? 32768u : 0u);
        uint32_t sB = sA + 16384;
#pragma unroll
        for (int ks = 0; ks < 4; ks++) {
            int kb = ks*32;
            uint32_t a[4][4], b[4][2];
#pragma unroll
            for (int mt = 0; mt < 4; mt++) {
                int row = warp_m*64 + mt*16 + (lane & 15);
                uint32_t ad = sA + SWZ128((uint32_t)(row*128 + kb + ((lane >> 4) << 4)));
                ldsm4(a[mt][0], a[mt][1], a[mt][2], a[mt][3], ad);
            }
#pragma unroll
            for (int nt = 0; nt < 4; nt++) {
                int row = warp_n*32 + nt*8 + (lane & 7);
                uint32_t ad = sB + SWZ128((uint32_t)(row*128 + kb + (((lane >> 3) & 1) << 4)));
                ldsm2(b[nt][0], b[nt][1], ad);
            }
#pragma unroll
            for (int mt = 0; mt < 4; mt++)
#pragma unroll
                for (int nt = 0; nt < 4; nt++)
                    mma16816(acc[mt][nt], a[mt], b[nt]);
        }
        __syncthreads();
    }

#pragma unroll
    for (int mt = 0; mt < 4; mt++) {
        int r0 = bm + warp_m*64 + mt*16 + (lane >> 2);
#pragma unroll
        for (int nt = 0; nt < 4; nt++) {
            int c0 = bn + warp_n*32 + nt*8 + ((lane & 3) << 1);
            if (Ch) {
                *(__half2*)&Ch[(size_t)r0*ldc + c0] =
                    __floats2half2_rn(acc[mt][nt][0], acc[mt][nt][1]);
                *(__half2*)&Ch[(size_t)(r0+8)*ldc + c0] =
                    __floats2half2_rn(acc[mt][nt][2], acc[mt][nt][3]);
            } else if (Uh && c0 < u_cols) {
                *(__half2*)&Uh[(size_t)r0*u_cols + c0] =
                    __floats2half2_rn(acc[mt][nt][0], acc[mt][nt][1]);
                *(__half2*)&Uh[(size_t)(r0+8)*u_cols + c0] =
                    __floats2half2_rn(acc[mt][nt][2], acc[mt][nt][3]);
            } else {
                *(float2*)&C[(size_t)r0*ldc + c0]     = make_float2(acc[mt][nt][0], acc[mt][nt][1]);
                *(float2*)&C[(size_t)(r0+8)*ldc + c0] = make_float2(acc[mt][nt][2], acc[mt][nt][3]);
            }
        }
    }

    if (psum) {
#pragma unroll
        for (int nt = 0; nt < 4; nt++) {
            float s0=0.f, s1=0.f, q0=0.f, q1=0.f;
#pragma unroll
            for (int mt = 0; mt < 4; mt++) {
                float v0=acc[mt][nt][0], v1=acc[mt][nt][1];
                float v2=acc[mt][nt][2], v3=acc[mt][nt][3];
                s0 += v0+v2; s1 += v1+v3;
                q0 += v0*v0 + v2*v2; q1 += v1*v1 + v3*v3;
            }
#pragma unroll
            for (int off = 16; off >= 4; off >>= 1) {
                s0 += __shfl_down_sync(0xffffffffu, s0, off);
                s1 += __shfl_down_sync(0xffffffffu, s1, off);
                q0 += __shfl_down_sync(0xffffffffu, q0, off);
                q1 += __shfl_down_sync(0xffffffffu, q1, off);
            }
            if (lane < 4) {
                int c0 = bn + warp_n*32 + nt*8 + lane*2;
                atomicAdd(&psum[c0],     s0);
                atomicAdd(&psum[c0+1],   s1);
                atomicAdd(&psumsq[c0],   q0);
                atomicAdd(&psumsq[c0+1], q1);
            }
        }
    }
}

// ------------------------- block-1 projection (K=3) -------------------------
__global__ __launch_bounds__(256) void uv1_kernel(const float* __restrict__ ft) {
    int p = blockIdx.x*2 + (threadIdx.x >> 7);
    int o = threadIdx.x & 127;
    float x0 = ft[p*3], x1 = ft[p*3+1], x2 = ft[p*3+2];
    float r = x0*d_wcomb[o*3] + x1*d_wcomb[o*3+1] + x2*d_wcomb[o*3+2];
    if (o < 64) d_uh[(size_t)p*64 + o] = __float2half_rn(r);
    else        d_uv[(size_t)p*128 + o] = r;
}

// --------------------- prep: zero stats + split all weights -----------------
__device__ __forceinline__ void split_w(const float* __restrict__ w, int C, int O,
                                        int j, __half* dh, __half* dl) {
    int r = j / C, c = j - r*C;
    float v = (r < O) ? w[r*2*C + c]
                      : (w[(r-O)*2*C + C + c] - w[(r-O)*2*C + c]);
    __half hi = __float2half_rn(v);
    dh[j] = hi;
    dl[j] = __float2half_rn(v - __half2float(hi));
}

__global__ void prep_all(const float* __restrict__ w1, const float* __restrict__ w2,
                         const float* __restrict__ w3, const float* __restrict__ w4,
                         const float* __restrict__ w5) {
    int i = blockIdx.x*256 + threadIdx.x;
    if (i < 1024) {
        d_sum[i] = 0.0; d_sumsq[i] = 0.0;
        d_psum[i] = 0.f; d_psumsq[i] = 0.f;
        if (i < 4) d_gcnt[i] = 0u;
    } else if (i < 1408) {
        int j = i - 1024;
        int r = j / 3, c = j - r*3;
        float v = (r < 64) ? w1[r*6 + c] : (w1[(r-64)*6 + 3 + c] - w1[(r-64)*6 + c]);
        d_wcomb[j] = v;
    } else if (i < 9600) {
        split_w(w2, 64, 64, i - 1408, d_wch, d_wcl);
    } else if (i < 25984) {
        split_w(w3, 64, 128, i - 9600, d_wch + 8192, d_wcl + 8192);
    } else if (i < 91520) {
        split_w(w4, 128, 256, i - 25984, d_wch + 24576, d_wcl + 24576);
    } else if (i < 615808) {
        int j = i - 91520;
        d_w5h[j] = __float2half_rn(w5[j]);
    }
}

// ---- gather + BN stats (fp16 u, float2 lanes) + last-block BN coefs --------
__global__ __launch_bounds__(256) void gather_kernel(int O, int iters, int soff,
                                                     int blk,
                                                     const float* __restrict__ gw,
                                                     const float* __restrict__ bw,
                                                     float invcnt) {
    int tpp = O >> 1;
    int groups = 256 / tpp;
    int g = threadIdx.x / tpp;
    int c2 = threadIdx.x - g*tpp;
    int ppb = groups * iters;
    int p0 = blockIdx.x * ppb;
    int W2 = 2*O;
    float sx=0.f, sy=0.f, qx=0.f, qy=0.f;
    for (int it = 0; it < iters; it++) {
        int p = p0 + it*groups + g;
        int rbase = (p >> 11) << 11;
        const int* ip = d_idx + p*KNN;
        float s1x=0.f, s1y=0.f, s2x=0.f, s2y=0.f;
        float mxx=-3.4e38f, mxy=-3.4e38f, mnx=3.4e38f, mny=3.4e38f;
#pragma unroll
        for (int k = 0; k < KNN; k++) {
            int m = ip[k];
            float2 u = __half22float2(
                *(const __half2*)&d_uh[(size_t)(rbase + m)*O + 2*c2]);
            s1x += u.x; s1y += u.y;
            s2x += u.x*u.x; s2y += u.y*u.y;
            mxx = fmaxf(mxx, u.x); mxy = fmaxf(mxy, u.y);
            mnx = fminf(mnx, u.x); mny = fminf(mny, u.y);
        }
        float2 v = *(const float2*)&d_uv[(size_t)p*W2 + O + 2*c2];
        *(float2*)&d_umax[(size_t)p*O + 2*c2] = make_float2(mxx, mxy);
        *(float2*)&d_umin[(size_t)p*O + 2*c2] = make_float2(mnx, mny);
        sx += s1x + 20.f*v.x;  sy += s1y + 20.f*v.y;
        qx += s2x + 2.f*v.x*s1x + 20.f*v.x*v.x;
        qy += s2y + 2.f*v.y*s1y + 20.f*v.y*v.y;
    }
    __shared__ float ssx[256], ssy[256], sqx[256], sqy[256];
    ssx[threadIdx.x] = sx; ssy[threadIdx.x] = sy;
    sqx[threadIdx.x] = qx; sqy[threadIdx.x] = qy;
    __syncthreads();
    for (int s = groups >> 1; s >= 1; s >>= 1) {
        if (g < s) {
            int j = threadIdx.x + s*tpp;
            ssx[threadIdx.x] += ssx[j]; ssy[threadIdx.x] += ssy[j];
            sqx[threadIdx.x] += sqx[j]; sqy[threadIdx.x] += sqy[j];
        }
        __syncthreads();
    }
    if (g == 0) {
        atomicAdd(&d_sum[soff + 2*c2],     (double)ssx[c2]);
        atomicAdd(&d_sum[soff + 2*c2+1],   (double)ssy[c2]);
        atomicAdd(&d_sumsq[soff + 2*c2],   (double)sqx[c2]);
        atomicAdd(&d_sumsq[soff + 2*c2+1], (double)sqy[c2]);
        __threadfence();
    }
    __syncthreads();
    __shared__ int is_last;
    if (threadIdx.x == 0) {
        unsigned old = atomicAdd(&d_gcnt[blk], 1u);
        is_last = (old == gridDim.x - 1u) ? 1 : 0;
    }
    __syncthreads();
    if (is_last && threadIdx.x < O) {
        int o = threadIdx.x;
        __threadfence();
        float mean = (float)(d_sum[soff+o]   * (double)invcnt);
        float msq  = (float)(d_sumsq[soff+o] * (double)invcnt);
        float var  = fmaxf(msq - mean*mean, 0.f);
        float sc = gw[o] * rsqrtf(var + 1e-5f);
        d_bnsc[soff+o] = sc;
        d_bnsh[soff+o] = bw[o] - mean*sc;
    }
}

// ------------------ edge_out (2 channels / thread, hoisted coefs) -----------
__global__ void edge_out(int O, int coff, int soff) {
    int i = blockIdx.x*256 + threadIdx.x;      // one per 2 channels
    int half_O = O >> 1;
    if (i < BNT*half_O) {
        int p = i / half_O, c2 = i - p*half_O;
        int o = 2*c2;
        float2 sc = *(const float2*)&d_bnsc[soff+o];
        float2 sh = *(const float2*)&d_bnsh[soff+o];
        float2 umx = *(const float2*)&d_umax[(size_t)p*O + o];
        float2 umn = *(const float2*)&d_umin[(size_t)p*O + o];
        float2 v   = *(const float2*)&d_uv[(size_t)p*(2*O) + O + o];
        float e0 = (sc.x >= 0.f) ? umx.x : umn.x;
        float e1 = (sc.y >= 0.f) ? umx.y : umn.y;
        float t0 = ftanh((v.x + e0)*sc.x + sh.x);
        float t1 = ftanh((v.y + e1)*sc.y + sh.y);
        __half2 hi = __floats2half2_rn(t0, t1);
        float r0 = __half2float(__low2half(hi));
        float r1 = __half2float(__high2half(hi));
        __half2 lo = __floats2half2_rn(t0 - r0, t1 - r1);
        size_t cidx = (size_t)p*512 + coff + o;
        *(__half2*)&d_cat_hi[cidx] = hi;
        *(__half2*)&d_cat_lo[cidx] = lo;
    }
}

// ------------------------- head: final reduce --------------------------------
__global__ __launch_bounds__(256) void final5(const float* __restrict__ g5,
                                              const float* __restrict__ b5,
                                              float* __restrict__ out) {
    int ol = threadIdx.x & 31;
    int row = threadIdx.x >> 5;
    int b = blockIdx.y;
    int o = blockIdx.x*32 + ol;
    float inv = 1.f / (float)BNT;
    float mean = d_psum[o] * inv;
    float var = fmaxf(d_psumsq[o]*inv - mean*mean, 0.f);
    float sc = g5[o] * rsqrtf(var + 1e-5f);
    float sh = b5[o] - mean*sc;
    const __half* hp = &d_h5[(size_t)(b*NPTS)*1024 + o];
    float mx0=-3.4e38f, mx1=-3.4e38f, mx2=-3.4e38f, mx3=-3.4e38f;
    float s0=0.f, s1=0.f, s2=0.f, s3=0.f;
    for (int n = row; n < NPTS; n += 32) {
        float z0 = __half2float(hp[(size_t)n*1024]);
        float z1 = __half2float(hp[(size_t)(n+8)*1024]);
        float z2 = __half2float(hp[(size_t)(n+16)*1024]);
        float z3 = __half2float(hp[(size_t)(n+24)*1024]);
        float t0 = ftanh_hw(z0*sc + sh);
        float t1 = ftanh_hw(z1*sc + sh);
        float t2 = ftanh_hw(z2*sc + sh);
        float t3 = ftanh_hw(z3*sc + sh);
        mx0 = fmaxf(mx0, t0); s0 += t0;
        mx1 = fmaxf(mx1, t1); s1 += t1;
        mx2 = fmaxf(mx2, t2); s2 += t2;
        mx3 = fmaxf(mx3, t3); s3 += t3;
    }
    float mx = fmaxf(fmaxf(mx0, mx1), fmaxf(mx2, mx3));
    float sm = (s0 + s1) + (s2 + s3);
    __shared__ float smx[8][32], ssm[8][32];
    smx[row][ol] = mx; ssm[row][ol] = sm;
    __syncthreads();
    if (row == 0) {
#pragma unroll
        for (int r=1;r<8;r++){ mx = fmaxf(mx, smx[r][ol]); sm += ssm[r][ol]; }
        out[b*2048 + o]        = mx;
        out[b*2048 + 1024 + o] = sm * (1.f/NPTS);
    }
}

// ------------------------------- launch -------------------------------------
#define GEMM_SMEM 65536

extern "C" void kernel_launch(void* const* d_in, const int* in_sizes, int n_in,
                              void* d_out, int out_size) {
    const float* x  = (const float*)d_in[0];
    const float* ft = (const float*)d_in[1];
    const float* W[4]  = {(const float*)d_in[2],  (const float*)d_in[5],
                          (const float*)d_in[8],  (const float*)d_in[11]};
    const float* G[4]  = {(const float*)d_in[3],  (const float*)d_in[6],
                          (const float*)d_in[9],  (const float*)d_in[12]};
    const float* Bv[4] = {(const float*)d_in[4],  (const float*)d_in[7],
                          (const float*)d_in[10], (const float*)d_in[13]};
    const float* w5 = (const float*)d_in[14];
    const float* g5 = (const float*)d_in[15];
    const float* b5 = (const float*)d_in[16];
    float* out = (float*)d_out;

    cudaFuncSetAttribute(gemm_mma, cudaFuncAttributeMaxDynamicSharedMemorySize,
                         GEMM_SMEM);

    void *puv, *puh, *pch, *pcl, *ph5, *pwch, *pwcl, *pw5h, *pps, *ppq;
    cudaGetSymbolAddress(&puv,  d_uv);
    cudaGetSymbolAddress(&puh,  d_uh);
    cudaGetSymbolAddress(&pch,  d_cat_hi);
    cudaGetSymbolAddress(&pcl,  d_cat_lo);
    cudaGetSymbolAddress(&ph5,  d_h5);
    cudaGetSymbolAddress(&pwch, d_wch);
    cudaGetSymbolAddress(&pwcl, d_wcl);
    cudaGetSymbolAddress(&pw5h, d_w5h);
    cudaGetSymbolAddress(&pps,  d_psum);
    cudaGetSymbolAddress(&ppq,  d_psumsq);
    float* uvP = (float*)puv;
    __half* uhP = (__half*)puh;
    __half* chP = (__half*)pch;
    __half* clP = (__half*)pcl;
    __half* h5P = (__half*)ph5;
    __half* wchP = (__half*)pwch;
    __half* wclP = (__half*)pwcl;
    __half* w5hP = (__half*)pw5h;

    prep_all<<<2406, 256>>>(W[0], W[1], W[2], W[3], w5);
    knn_kernel<<<BATCH*16, 128>>>(x);

    const int Cin[4]  = {3, 64, 64, 128};
    const int Oc[4]   = {64, 64, 128, 256};
    const int coff[4] = {0, 64, 128, 256};
    const int boff[4] = {0, 0, 8192, 24576};

    for (int blk = 0; blk < 4; blk++) {
        int C = Cin[blk], O = Oc[blk];
        if (blk == 0) {
            uv1_kernel<<<BNT/2, 256>>>(ft);
        } else {
            int cin = coff[blk-1];
            dim3 gg(2*O/128, BNT/128);
            gemm_mma<<<gg, 256, GEMM_SMEM>>>(chP + cin, clP + cin, 512,
                                             wchP + boff[blk], wclP + boff[blk], C,
                                             uvP, nullptr, 2*O, C, 3, uhP, O,
                                             nullptr, nullptr);
        }
        int iters = 4;
        int tpp = O/2, groups = 256/tpp, ppb = groups*iters;
        gather_kernel<<<BNT/ppb, 256>>>(O, iters, blk*256, blk,
                                        G[blk], Bv[blk], 1.f/((float)BNT*KNN));
        edge_out<<<(BNT*(O/2) + 255)/256, 256>>>(O, coff[blk], blk*256);
    }

    dim3 g5g(1024/128, BNT/128);
    gemm_mma<<<g5g, 256, GEMM_SMEM>>>(chP, nullptr, 512, w5hP, nullptr, 512,
                                      nullptr, h5P, 1024, 512, 1, nullptr, 0,
                                      (float*)pps, (float*)ppq);
    dim3 fg(32, BATCH);
    final5<<<fg, 256>>>(g5, b5, out);
}